// round 1
// baseline (speedup 1.0000x reference)
#include <cuda_runtime.h>

#define TLEN 4096
#define NH 32
#define HS 64
#define DIM (NH*HS)

// Grid: 128 blocks = 32 heads x 4 row-quarters. Block: 128 threads =
// 16 rows x 8 lanes/row; each lane owns 8 contiguous j-elements of the
// state row in registers. Per step:
//   sa_i  = sum_j s[i,j]*a[j]           (partial dot + 3x shfl_xor reduce)
//   s[i,j] = s[i,j]*w[j] + v[i]*k[j] + sa_i*b[j]
//   y[i]  = sum_j s[i,j]*r[j]           (partial dot + 3x shfl_xor reduce)
// Per-step operands (w,k,a,b,r: 64 floats; v: 16 floats) are prefetched
// into registers one step ahead and committed to smem, hiding gmem latency.
__global__ void __launch_bounds__(128, 1) wkv7_kernel(
    const float* __restrict__ rr, const float* __restrict__ ww,
    const float* __restrict__ kk, const float* __restrict__ vv_,
    const float* __restrict__ aa, const float* __restrict__ bb,
    const float* __restrict__ s0, float* __restrict__ y, float* __restrict__ sout)
{
    const int blk  = blockIdx.x;
    const int h    = blk >> 2;          // head
    const int q    = blk & 3;           // row quarter
    const int tid  = threadIdx.x;
    const int rloc = tid >> 3;          // 0..15 local row
    const int lane8 = tid & 7;          // 0..7 j-split lane
    const int row  = q * 16 + rloc;     // 0..63 row within head
    const int j0   = lane8 * 8;

    // State slice in registers: s[row][j0 .. j0+7]
    float s[8];
    {
        const float* sp = s0 + ((size_t)h * HS + row) * HS + j0;
        #pragma unroll
        for (int jj = 0; jj < 8; jj++) s[jj] = sp[jj];
    }

    __shared__ float sw[HS], sk[HS], sa[HS], sb[HS], sr[HS], sv[16];

    const int hbase = h * HS;
    const int u = tid - 64;

    // Prologue: prefetch t=0 operands into registers.
    float l0, l1, l2;
    {
        const int base = hbase; // t = 0
        if (tid < 64) {
            l0 = ww[base + tid]; l1 = kk[base + tid]; l2 = rr[base + tid];
        } else {
            l0 = aa[base + u];   l1 = bb[base + u];
            l2 = (u < 16) ? vv_[base + q * 16 + u] : 0.f;
        }
    }

    for (int t = 0; t < TLEN; t++) {
        __syncthreads();                  // previous step's smem readers done
        if (tid < 64) {
            sw[tid] = l0; sk[tid] = l1; sr[tid] = l2;
        } else {
            sa[u] = l0; sb[u] = l1;
            if (u < 16) sv[u] = l2;
        }
        __syncthreads();

        // Prefetch t+1 (latency overlaps the compute below).
        {
            const int tn   = (t + 1 < TLEN) ? (t + 1) : t;
            const int base = tn * DIM + hbase;
            if (tid < 64) {
                l0 = ww[base + tid]; l1 = kk[base + tid]; l2 = rr[base + tid];
            } else {
                l0 = aa[base + u];   l1 = bb[base + u];
                if (u < 16) l2 = vv_[base + q * 16 + u];
            }
        }

        // sa_i partial dot + reduce across the 8 lanes of this row.
        float sacc = 0.f;
        #pragma unroll
        for (int jj = 0; jj < 8; jj++) sacc += s[jj] * sa[j0 + jj];
        sacc += __shfl_xor_sync(0xffffffffu, sacc, 1);
        sacc += __shfl_xor_sync(0xffffffffu, sacc, 2);
        sacc += __shfl_xor_sync(0xffffffffu, sacc, 4);

        // sa-independent part computed here -> ptxas overlaps it with the
        // shfl chain above (no data dependence).
        const float vrow = sv[rloc];
        float pu[8];
        #pragma unroll
        for (int jj = 0; jj < 8; jj++)
            pu[jj] = fmaf(s[jj], sw[j0 + jj], vrow * sk[j0 + jj]);

        float yacc = 0.f;
        #pragma unroll
        for (int jj = 0; jj < 8; jj++) {
            float sn = fmaf(sacc, sb[j0 + jj], pu[jj]);
            s[jj] = sn;
            yacc = fmaf(sn, sr[j0 + jj], yacc);
        }
        yacc += __shfl_xor_sync(0xffffffffu, yacc, 1);
        yacc += __shfl_xor_sync(0xffffffffu, yacc, 2);
        yacc += __shfl_xor_sync(0xffffffffu, yacc, 4);

        if (lane8 == 0) y[t * DIM + hbase + row] = yacc;
    }

    // Final state out.
    float* sp = sout + ((size_t)h * HS + row) * HS + j0;
    #pragma unroll
    for (int jj = 0; jj < 8; jj++) sp[jj] = s[jj];
}

extern "C" void kernel_launch(void* const* d_in, const int* in_sizes, int n_in,
                              void* d_out, int out_size) {
    // Inputs (metadata order): [seq_length?], r, w, k, v, a, b, state2
    int o = (n_in >= 8) ? 1 : 0;
    const float* r  = (const float*)d_in[o + 0];
    const float* w  = (const float*)d_in[o + 1];
    const float* k  = (const float*)d_in[o + 2];
    const float* v  = (const float*)d_in[o + 3];
    const float* a  = (const float*)d_in[o + 4];
    const float* b  = (const float*)d_in[o + 5];
    const float* s0 = (const float*)d_in[o + 6];

    float* y    = (float*)d_out;                    // x: [T, H, 1, N]
    float* sout = y + (size_t)TLEN * DIM;           // state2_out: [H, N, N]

    wkv7_kernel<<<128, 128>>>(r, w, k, v, a, b, s0, y, sout);
}

// round 2
// speedup vs baseline: 1.7614x; 1.7614x over previous
#include <cuda_runtime.h>

#define TLEN 4096
#define NH 32
#define HS 64
#define DIM (NH*HS)

// Grid: 128 blocks = 32 heads x 4 row-quarters. Block: 128 threads = 4
// independent warps (no smem, no __syncthreads). Each warp owns 4 rows x 8
// lanes; each lane holds 8 contiguous j-elements of its row's state in regs.
//
// Latency plan: operands (w,k,a,b,r: 8 floats/lane; v: 1/lane) are register
// double-buffered TWO steps deep (LDG for t+2 issued right after buffer t is
// consumed), and prefetch.global.L2 runs EIGHT steps ahead so those LDGs hit
// L2/L1 instead of DRAM. Recurrent critical path per step is just:
//   pairwise dot (16cyc) -> 3x shfl_xor (78) -> 1 FMA  ~= 100 cyc.

#define LD8(dst, base, tt) do { \
    const float4* _p = (const float4*)((base) + (size_t)(tt) * DIM); \
    float4 _x = _p[0]; float4 _y = _p[1]; \
    dst[0]=_x.x; dst[1]=_x.y; dst[2]=_x.z; dst[3]=_x.w; \
    dst[4]=_y.x; dst[5]=_y.y; dst[6]=_y.z; dst[7]=_y.w; } while(0)

__global__ void __launch_bounds__(128, 1) wkv7_kernel(
    const float* __restrict__ rr, const float* __restrict__ ww,
    const float* __restrict__ kk, const float* __restrict__ vv_,
    const float* __restrict__ aa, const float* __restrict__ bb,
    const float* __restrict__ s0, float* __restrict__ y, float* __restrict__ sout)
{
    const int blk   = blockIdx.x;
    const int h     = blk >> 2;
    const int q     = blk & 3;
    const int tid   = threadIdx.x;
    const int rloc  = tid >> 3;         // 0..15
    const int lane8 = tid & 7;          // 0..7
    const int row   = q * 16 + rloc;    // 0..63
    const int j0    = lane8 * 8;
    const int hbase = h * HS;

    const float* pw = ww  + hbase + j0;
    const float* pk = kk  + hbase + j0;
    const float* pa = aa  + hbase + j0;
    const float* pb = bb  + hbase + j0;
    const float* pr = rr  + hbase + j0;
    const float* pv = vv_ + hbase + row;

    // State slice in registers
    float s[8];
    {
        const float* sp = s0 + ((size_t)h * HS + row) * HS + j0;
        #pragma unroll
        for (int jj = 0; jj < 8; jj++) s[jj] = sp[jj];
    }

    // L2 prefetch pointer: 12 cache lines per head per step
    // lanes 0..11 -> {w,k,a,b,r,v} x {line0, line1}
    const int lane = tid & 31;
    const float* pfp = 0;
    if (lane < 12) {
        const float* base =
            (lane < 2) ? ww : (lane < 4) ? kk : (lane < 6) ? aa :
            (lane < 8) ? bb : (lane < 10) ? rr : vv_;
        pfp = base + hbase + (lane & 1) * 32;
    }

    float w0[8], k0[8], a0[8], b0[8], r0[8], v0;
    float w1[8], k1[8], a1[8], b1[8], r1[8], v1;

    LD8(w0, pw, 0); LD8(k0, pk, 0); LD8(a0, pa, 0);
    LD8(b0, pb, 0); LD8(r0, pr, 0); v0 = pv[0];
    LD8(w1, pw, 1); LD8(k1, pk, 1); LD8(a1, pa, 1);
    LD8(b1, pb, 1); LD8(r1, pr, 1); v1 = pv[(size_t)1 * DIM];

#define STEP(W, K, A, B, R, V, T) do { \
    float c0 = fmaf(s[1], A[1], s[0] * A[0]); \
    float c1 = fmaf(s[3], A[3], s[2] * A[2]); \
    float c2 = fmaf(s[5], A[5], s[4] * A[4]); \
    float c3 = fmaf(s[7], A[7], s[6] * A[6]); \
    float sacc = (c0 + c1) + (c2 + c3); \
    sacc += __shfl_xor_sync(0xffffffffu, sacc, 1); \
    sacc += __shfl_xor_sync(0xffffffffu, sacc, 2); \
    sacc += __shfl_xor_sync(0xffffffffu, sacc, 4); \
    float pu[8]; \
    _Pragma("unroll") \
    for (int jj = 0; jj < 8; jj++) \
        pu[jj] = fmaf(s[jj], W[jj], V * K[jj]); \
    _Pragma("unroll") \
    for (int jj = 0; jj < 8; jj++) \
        s[jj] = fmaf(sacc, B[jj], pu[jj]); \
    float y0 = fmaf(s[1], R[1], s[0] * R[0]); \
    float y1 = fmaf(s[3], R[3], s[2] * R[2]); \
    float y2 = fmaf(s[5], R[5], s[4] * R[4]); \
    float y3 = fmaf(s[7], R[7], s[6] * R[6]); \
    float yacc = (y0 + y1) + (y2 + y3); \
    yacc += __shfl_xor_sync(0xffffffffu, yacc, 1); \
    yacc += __shfl_xor_sync(0xffffffffu, yacc, 2); \
    yacc += __shfl_xor_sync(0xffffffffu, yacc, 4); \
    if (lane8 == 0) y[(size_t)(T) * DIM + hbase + row] = yacc; \
} while(0)

    for (int t = 0; t < TLEN; t += 2) {
        // L2 prefetch 8 steps ahead (one predicated instr per lane<12)
        if (pfp) {
            int tp = t + 8;  if (tp > TLEN - 1) tp = TLEN - 1;
            asm volatile("prefetch.global.L2 [%0];" :: "l"(pfp + (size_t)tp * DIM));
            tp = t + 9;      if (tp > TLEN - 1) tp = TLEN - 1;
            asm volatile("prefetch.global.L2 [%0];" :: "l"(pfp + (size_t)tp * DIM));
        }

        STEP(w0, k0, a0, b0, r0, v0, t);
        {
            int tn = t + 2; if (tn > TLEN - 1) tn = TLEN - 1;
            LD8(w0, pw, tn); LD8(k0, pk, tn); LD8(a0, pa, tn);
            LD8(b0, pb, tn); LD8(r0, pr, tn); v0 = pv[(size_t)tn * DIM];
        }
        STEP(w1, k1, a1, b1, r1, v1, t + 1);
        {
            int tn = t + 3; if (tn > TLEN - 1) tn = TLEN - 1;
            LD8(w1, pw, tn); LD8(k1, pk, tn); LD8(a1, pa, tn);
            LD8(b1, pb, tn); LD8(r1, pr, tn); v1 = pv[(size_t)tn * DIM];
        }
    }

    // Final state out
    float* sp = sout + ((size_t)h * HS + row) * HS + j0;
    #pragma unroll
    for (int jj = 0; jj < 8; jj++) sp[jj] = s[jj];
}

extern "C" void kernel_launch(void* const* d_in, const int* in_sizes, int n_in,
                              void* d_out, int out_size) {
    int o = (n_in >= 8) ? 1 : 0;
    const float* r  = (const float*)d_in[o + 0];
    const float* w  = (const float*)d_in[o + 1];
    const float* k  = (const float*)d_in[o + 2];
    const float* v  = (const float*)d_in[o + 3];
    const float* a  = (const float*)d_in[o + 4];
    const float* b  = (const float*)d_in[o + 5];
    const float* s0 = (const float*)d_in[o + 6];

    float* y    = (float*)d_out;                  // x: [T, H, 1, N]
    float* sout = y + (size_t)TLEN * DIM;         // state2_out: [H, N, N]

    wkv7_kernel<<<128, 128>>>(r, w, k, v, a, b, s0, y, sout);
}

// round 3
// speedup vs baseline: 2.5436x; 1.4441x over previous
#include <cuda_runtime.h>
#include <cstdint>

#define TLEN 4096
#define NH 32
#define HS 64
#define DIM (NH*HS)
#define DEPTH 8
#define STRIDE 336   // floats per ring slot: w64|k64|a64|b64|r64|v4|pad

// Grid: 128 blocks = 32 heads x 4 row-quarters. Block: 128 threads = 4
// independent warps, no block barriers. Each warp: 4 rows x 8 lanes, each
// lane holds 8 j-elements of its row's state in registers.
//
// Operand staging: per-warp private cp.async ring in smem, DEPTH=8 steps
// ahead (covers DRAM latency ~577cyc). Per step each lane issues 3x 16B
// LDGSTS; consumer does cp.async.wait_group + __syncwarp, then LDS the
// NEXT step's operands into registers (1 step of LDS cover).

__device__ __forceinline__ uint32_t smem_addr(const void* p) {
    return (uint32_t)__cvta_generic_to_shared(p);
}

struct Ops { float w[8], k[8], a[8], b[8], r[8], v; };

__global__ void __launch_bounds__(128, 1) wkv7_kernel(
    const float* __restrict__ rr, const float* __restrict__ ww,
    const float* __restrict__ kk, const float* __restrict__ vv_,
    const float* __restrict__ aa, const float* __restrict__ bb,
    const float* __restrict__ s0, float* __restrict__ y, float* __restrict__ sout)
{
    const int blk   = blockIdx.x;
    const int h     = blk >> 2;
    const int q     = blk & 3;
    const int tid   = threadIdx.x;
    const int warp  = tid >> 5;
    const int lane  = tid & 31;
    const int lane8 = tid & 7;
    const int rloc  = tid >> 3;          // 0..15 (warp*4 + lane>>3)
    const int row   = q * 16 + rloc;     // 0..63
    const int j0    = lane8 * 8;
    const int vidx  = lane >> 3;         // 0..3 row-within-warp
    const int hbase = h * HS;

    __shared__ float ring[4][DEPTH][STRIDE];

    // State slice in registers
    float s[8];
    {
        const float* sp = s0 + ((size_t)h * HS + row) * HS + j0;
        #pragma unroll
        for (int jj = 0; jj < 8; jj++) s[jj] = sp[jj];
    }

    // Per-lane cp.async source pointers and dst offsets (floats within slot)
    const float *g1, *g2, *g3 = 0;
    uint32_t o1, o2, o3 = 0;
    if (lane < 16) { g1 = ww + hbase + lane * 4;        o1 = 0   + lane * 4; }
    else           { g1 = kk + hbase + (lane - 16) * 4; o1 = 64  + (lane - 16) * 4; }
    if (lane < 16) { g2 = aa + hbase + lane * 4;        o2 = 128 + lane * 4; }
    else           { g2 = bb + hbase + (lane - 16) * 4; o2 = 192 + (lane - 16) * 4; }
    if (lane < 16)      { g3 = rr + hbase + lane * 4;            o3 = 256 + lane * 4; }
    else if (lane == 16){ g3 = vv_ + hbase + q * 16 + warp * 4;  o3 = 320; }

#define ISSUE(tt, ss) do { \
    size_t _off = (size_t)(tt) * DIM; \
    uint32_t _sb = smem_addr(&ring[warp][ss][0]); \
    asm volatile("cp.async.cg.shared.global [%0], [%1], 16;" :: "r"(_sb + o1*4u), "l"(g1 + _off)); \
    asm volatile("cp.async.cg.shared.global [%0], [%1], 16;" :: "r"(_sb + o2*4u), "l"(g2 + _off)); \
    if (g3) asm volatile("cp.async.cg.shared.global [%0], [%1], 16;" :: "r"(_sb + o3*4u), "l"(g3 + _off)); \
    asm volatile("cp.async.commit_group;"); \
} while(0)

#define LOADREGS(R, ss) do { \
    const float* _sl = &ring[warp][ss][0]; \
    *(float4*)&R.w[0] = *(const float4*)(_sl + j0); \
    *(float4*)&R.w[4] = *(const float4*)(_sl + j0 + 4); \
    *(float4*)&R.k[0] = *(const float4*)(_sl + 64 + j0); \
    *(float4*)&R.k[4] = *(const float4*)(_sl + 64 + j0 + 4); \
    *(float4*)&R.a[0] = *(const float4*)(_sl + 128 + j0); \
    *(float4*)&R.a[4] = *(const float4*)(_sl + 128 + j0 + 4); \
    *(float4*)&R.b[0] = *(const float4*)(_sl + 192 + j0); \
    *(float4*)&R.b[4] = *(const float4*)(_sl + 192 + j0 + 4); \
    *(float4*)&R.r[0] = *(const float4*)(_sl + 256 + j0); \
    *(float4*)&R.r[4] = *(const float4*)(_sl + 256 + j0 + 4); \
    R.v = _sl[320 + vidx]; \
} while(0)

#define STEP(R, T) do { \
    float c0 = fmaf(s[1], R.a[1], s[0] * R.a[0]); \
    float c1 = fmaf(s[3], R.a[3], s[2] * R.a[2]); \
    float c2 = fmaf(s[5], R.a[5], s[4] * R.a[4]); \
    float c3 = fmaf(s[7], R.a[7], s[6] * R.a[6]); \
    float sacc = (c0 + c1) + (c2 + c3); \
    sacc += __shfl_xor_sync(0xffffffffu, sacc, 1); \
    sacc += __shfl_xor_sync(0xffffffffu, sacc, 2); \
    sacc += __shfl_xor_sync(0xffffffffu, sacc, 4); \
    float pu[8]; \
    _Pragma("unroll") \
    for (int jj = 0; jj < 8; jj++) \
        pu[jj] = fmaf(s[jj], R.w[jj], R.v * R.k[jj]); \
    _Pragma("unroll") \
    for (int jj = 0; jj < 8; jj++) \
        s[jj] = fmaf(sacc, R.b[jj], pu[jj]); \
    float y0 = fmaf(s[1], R.r[1], s[0] * R.r[0]); \
    float y1 = fmaf(s[3], R.r[3], s[2] * R.r[2]); \
    float y2 = fmaf(s[5], R.r[5], s[4] * R.r[4]); \
    float y3 = fmaf(s[7], R.r[7], s[6] * R.r[6]); \
    float yacc = (y0 + y1) + (y2 + y3); \
    yacc += __shfl_xor_sync(0xffffffffu, yacc, 1); \
    yacc += __shfl_xor_sync(0xffffffffu, yacc, 2); \
    yacc += __shfl_xor_sync(0xffffffffu, yacc, 4); \
    if (lane8 == 0) y[(size_t)(T) * DIM + hbase + row] = yacc; \
} while(0)

    // Prologue: fill ring with times 0..DEPTH-1
    #pragma unroll
    for (int i = 0; i < DEPTH; i++) ISSUE(i, i);

    asm volatile("cp.async.wait_group 7;");
    __syncwarp();
    Ops A, B;
    LOADREGS(A, 0);

    for (int t = 0; t < TLEN; t += 2) {
        asm volatile("cp.async.wait_group 6;");
        __syncwarp();
        LOADREGS(B, (t + 1) & (DEPTH - 1));
        STEP(A, t);
        {
            int tn = t + DEPTH; if (tn > TLEN - 1) tn = TLEN - 1;
            ISSUE(tn, t & (DEPTH - 1));
        }

        asm volatile("cp.async.wait_group 6;");
        __syncwarp();
        LOADREGS(A, (t + 2) & (DEPTH - 1));
        STEP(B, t + 1);
        {
            int tn = t + 1 + DEPTH; if (tn > TLEN - 1) tn = TLEN - 1;
            ISSUE(tn, (t + 1) & (DEPTH - 1));
        }
    }

    // Final state out
    float* sp = sout + ((size_t)h * HS + row) * HS + j0;
    #pragma unroll
    for (int jj = 0; jj < 8; jj++) sp[jj] = s[jj];
}

extern "C" void kernel_launch(void* const* d_in, const int* in_sizes, int n_in,
                              void* d_out, int out_size) {
    int o = (n_in >= 8) ? 1 : 0;
    const float* r  = (const float*)d_in[o + 0];
    const float* w  = (const float*)d_in[o + 1];
    const float* k  = (const float*)d_in[o + 2];
    const float* v  = (const float*)d_in[o + 3];
    const float* a  = (const float*)d_in[o + 4];
    const float* b  = (const float*)d_in[o + 5];
    const float* s0 = (const float*)d_in[o + 6];

    float* y    = (float*)d_out;                  // x: [T, H, 1, N]
    float* sout = y + (size_t)TLEN * DIM;         // state2_out: [H, N, N]

    wkv7_kernel<<<128, 128>>>(r, w, k, v, a, b, s0, y, sout);
}

// round 4
// speedup vs baseline: 2.5686x; 1.0098x over previous
#include <cuda_runtime.h>
#include <cstdint>

#define TLEN 4096
#define NH 32
#define HS 64
#define DIM (NH*HS)
#define DEPTH 8
#define STRIDE 336   // floats per ring slot: w64|k64|a64|b64|r64|v4|pad

// 128 blocks = 32 heads x 4 row-quarters; 4 independent warps/block (no block
// sync). Warp = 4 rows x 8 lanes; lane holds 8 j-elements of state (4x f32x2).
//
// Recurrence decomposition (removes shfl chain from the per-step cycle):
//   sa_{t+1} = A_t + sa_t*B_t + v_t*C_t
//   A_t = dot(S_t .* w_t, a_{t+1}),  B_t = dot(b_t, a_{t+1}),  C_t = dot(k_t, a_{t+1})
// y_t reduction + STG deferred one iteration (overlaps next step's chain).
// Operands staged per-warp via cp.async ring, DEPTH=8 ahead.

__device__ __forceinline__ uint32_t smem_u32(const void* p) {
    return (uint32_t)__cvta_generic_to_shared(p);
}

typedef unsigned long long u64;

#define MUL2(d,a,b)   asm("mul.rn.f32x2 %0, %1, %2;"      : "=l"(d) : "l"(a), "l"(b))
#define FMA2(d,a,b,c) asm("fma.rn.f32x2 %0, %1, %2, %3;"  : "=l"(d) : "l"(a), "l"(b), "l"(c))
#define PACK2(d,lo,hi)   asm("mov.b64 %0, {%1, %2};" : "=l"(d) : "f"(lo), "f"(hi))
#define UNPACK2(lo,hi,v) asm("mov.b64 {%0, %1}, %2;" : "=f"(lo), "=f"(hi) : "l"(v))

// packed dot of 4 x f32x2 -> scalar float
#define DOT8(res, X, Y) do { \
    u64 _p; MUL2(_p, X[0], Y[0]); FMA2(_p, X[1], Y[1], _p); \
    FMA2(_p, X[2], Y[2], _p);     FMA2(_p, X[3], Y[3], _p); \
    float _lo, _hi; UNPACK2(_lo, _hi, _p); res = _lo + _hi; } while(0)

#define RED8(x) do { \
    x += __shfl_xor_sync(0xffffffffu, x, 1); \
    x += __shfl_xor_sync(0xffffffffu, x, 2); \
    x += __shfl_xor_sync(0xffffffffu, x, 4); } while(0)

__global__ void __launch_bounds__(128, 1) wkv7_kernel(
    const float* __restrict__ rr, const float* __restrict__ ww,
    const float* __restrict__ kk, const float* __restrict__ vv_,
    const float* __restrict__ aa, const float* __restrict__ bb,
    const float* __restrict__ s0, float* __restrict__ y, float* __restrict__ sout)
{
    const int blk   = blockIdx.x;
    const int h     = blk >> 2;
    const int q     = blk & 3;
    const int tid   = threadIdx.x;
    const int warp  = tid >> 5;
    const int lane  = tid & 31;
    const int lane8 = tid & 7;
    const int rloc  = tid >> 3;
    const int row   = q * 16 + rloc;
    const int j0    = lane8 * 8;
    const int vidx  = lane >> 3;
    const int hbase = h * HS;

    __shared__ __align__(16) float ring[4][DEPTH][STRIDE];

    // State (packed): s2[i] = {s[2i], s[2i+1]}
    u64 s2[4];
    {
        const float* sp = s0 + ((size_t)h * HS + row) * HS + j0;
        const ulonglong2* p = (const ulonglong2*)sp;
        ulonglong2 x0 = p[0], x1 = p[1];
        s2[0] = x0.x; s2[1] = x0.y; s2[2] = x1.x; s2[3] = x1.y;
    }

    // cp.async lane routing
    const float *g1, *g2, *g3 = 0;
    uint32_t o1, o2, o3 = 0;
    if (lane < 16) { g1 = ww + hbase + lane * 4;        o1 = 0   + lane * 4; }
    else           { g1 = kk + hbase + (lane - 16) * 4; o1 = 64  + (lane - 16) * 4; }
    if (lane < 16) { g2 = aa + hbase + lane * 4;        o2 = 128 + lane * 4; }
    else           { g2 = bb + hbase + (lane - 16) * 4; o2 = 192 + (lane - 16) * 4; }
    if (lane < 16)      { g3 = rr + hbase + lane * 4;            o3 = 256 + lane * 4; }
    else if (lane == 16){ g3 = vv_ + hbase + q * 16 + warp * 4;  o3 = 320; }

#define ISSUE(tt, ss) do { \
    size_t _off = (size_t)(tt) * DIM; \
    uint32_t _sb = smem_u32(&ring[warp][ss][0]); \
    asm volatile("cp.async.cg.shared.global [%0], [%1], 16;" :: "r"(_sb + o1*4u), "l"(g1 + _off)); \
    asm volatile("cp.async.cg.shared.global [%0], [%1], 16;" :: "r"(_sb + o2*4u), "l"(g2 + _off)); \
    if (g3) asm volatile("cp.async.cg.shared.global [%0], [%1], 16;" :: "r"(_sb + o3*4u), "l"(g3 + _off)); \
    asm volatile("cp.async.commit_group;"); \
} while(0)

    // Prologue: fill ring slots 0..7 with t=0..7
    #pragma unroll
    for (int i = 0; i < DEPTH; i++) ISSUE(i, i);

    // sa_0 = dot(S_0, a_0): direct LDG of a_0
    float sa;
    {
        const float* ap = aa + hbase + j0;
        const ulonglong2* p = (const ulonglong2*)ap;
        ulonglong2 x0 = p[0], x1 = p[1];
        u64 a2i[4] = { x0.x, x0.y, x1.x, x1.y };
        DOT8(sa, s2, a2i);
        RED8(sa);
    }

    u64 yp2 = 0;  // deferred packed y partial (t=0 junk write is overwritten)

    for (int t = 0; t < TLEN; t++) {
        asm volatile("cp.async.wait_group 6;");
        __syncwarp();

        // Load operands for step t (w,k,b,r,v from slot t; a' = a_{t+1} from slot t+1)
        const float* sl  = &ring[warp][t & (DEPTH-1)][0];
        const float* sln = &ring[warp][(t+1) & (DEPTH-1)][0];
        u64 w2[4], k2[4], b2[4], r2[4], a2[4];
        {
            const ulonglong2* p;
            p = (const ulonglong2*)(sl + j0);        w2[0]=p[0].x; w2[1]=p[0].y; w2[2]=p[1].x; w2[3]=p[1].y;
            p = (const ulonglong2*)(sl + 64 + j0);   k2[0]=p[0].x; k2[1]=p[0].y; k2[2]=p[1].x; k2[3]=p[1].y;
            p = (const ulonglong2*)(sl + 192 + j0);  b2[0]=p[0].x; b2[1]=p[0].y; b2[2]=p[1].x; b2[3]=p[1].y;
            p = (const ulonglong2*)(sl + 256 + j0);  r2[0]=p[0].x; r2[1]=p[0].y; r2[2]=p[1].x; r2[3]=p[1].y;
            p = (const ulonglong2*)(sln + 128 + j0); a2[0]=p[0].x; a2[1]=p[0].y; a2[2]=p[1].x; a2[3]=p[1].y;
        }
        const float v = sl[320 + vidx];

        // Finalize deferred y_{t-1} (shfl latency overlaps this step's work)
        {
            float yl, yh; UNPACK2(yl, yh, yp2);
            float yv = yl + yh;
            RED8(yv);
            int tprev = (t > 0) ? (t - 1) : 0;
            if (lane8 == 0) y[(size_t)tprev * DIM + hbase + row] = yv;
        }

        // sw = S_t .* w_t   (feeds both A-dot and state update)
        u64 sw2[4];
        MUL2(sw2[0], s2[0], w2[0]); MUL2(sw2[1], s2[1], w2[1]);
        MUL2(sw2[2], s2[2], w2[2]); MUL2(sw2[3], s2[3], w2[3]);

        // A = dot(sw, a'), B = dot(b, a'), C = dot(k, a')  — three parallel chains
        float A, B, C;
        DOT8(A, sw2, a2); RED8(A);
        DOT8(B, b2,  a2); RED8(B);
        DOT8(C, k2,  a2); RED8(C);

        // State update: s' = sw + sa*b + v*k
        u64 v2, sa2;
        PACK2(v2, v, v);
        PACK2(sa2, sa, sa);
        #pragma unroll
        for (int i = 0; i < 4; i++) {
            u64 pu; FMA2(pu, v2, k2[i], sw2[i]);
            FMA2(s2[i], sa2, b2[i], pu);
        }

        // y partial (packed; reduced next iteration)
        MUL2(yp2, s2[0], r2[0]); FMA2(yp2, s2[1], r2[1], yp2);
        FMA2(yp2, s2[2], r2[2], yp2); FMA2(yp2, s2[3], r2[3], yp2);

        // Scalar sa recurrence: sa_{t+1} = A + sa*B + v*C
        sa = fmaf(sa, B, fmaf(v, C, A));

        // Refill ring
        int tn = t + DEPTH; if (tn > TLEN - 1) tn = TLEN - 1;
        ISSUE(tn, t & (DEPTH-1));
    }

    // Epilogue: finalize y_{TLEN-1}
    {
        float yl, yh; UNPACK2(yl, yh, yp2);
        float yv = yl + yh;
        RED8(yv);
        if (lane8 == 0) y[(size_t)(TLEN-1) * DIM + hbase + row] = yv;
    }

    // Final state out
    {
        float* sp = sout + ((size_t)h * HS + row) * HS + j0;
        ulonglong2* p = (ulonglong2*)sp;
        ulonglong2 x0, x1;
        x0.x = s2[0]; x0.y = s2[1]; x1.x = s2[2]; x1.y = s2[3];
        p[0] = x0; p[1] = x1;
    }
}

extern "C" void kernel_launch(void* const* d_in, const int* in_sizes, int n_in,
                              void* d_out, int out_size) {
    int o = (n_in >= 8) ? 1 : 0;
    const float* r  = (const float*)d_in[o + 0];
    const float* w  = (const float*)d_in[o + 1];
    const float* k  = (const float*)d_in[o + 2];
    const float* v  = (const float*)d_in[o + 3];
    const float* a  = (const float*)d_in[o + 4];
    const float* b  = (const float*)d_in[o + 5];
    const float* s0 = (const float*)d_in[o + 6];

    float* y    = (float*)d_out;                  // x: [T, H, 1, N]
    float* sout = y + (size_t)TLEN * DIM;         // state2_out: [H, N, N]

    wkv7_kernel<<<128, 128>>>(r, w, k, v, a, b, s0, y, sout);
}

// round 5
// speedup vs baseline: 3.3108x; 1.2889x over previous
#include <cuda_runtime.h>
#include <cstdint>

#define TLEN 4096
#define NH 32
#define HS 64
#define DIM (NH*HS)
#define DEPTH 8
#define STRIDE 336   // floats/slot: w64|k64|a64|b64|r64|v8|pad

// grid=128 (32 heads x 4 quarters), block=64 = 2 warps. Warp = 4 groups x 8
// lanes; each lane owns TWO rows' j-slices (16 state floats, packed f32x2).
// Operand bytes per lane serve 2 rows -> ~2.5x less L1TEX traffic than R4.
// Per-warp cp.async ring DEPTH=8 covers DRAM; a_t is register-prefetched one
// step ahead so the recurrent chain is dot->RED->update only.

__device__ __forceinline__ uint32_t smem_u32(const void* p) {
    return (uint32_t)__cvta_generic_to_shared(p);
}

typedef unsigned long long u64;

#define MUL2(d,a,b)   asm("mul.rn.f32x2 %0, %1, %2;"     : "=l"(d) : "l"(a), "l"(b))
#define FMA2(d,a,b,c) asm("fma.rn.f32x2 %0, %1, %2, %3;" : "=l"(d) : "l"(a), "l"(b), "l"(c))
#define PACK2(d,lo,hi)   asm("mov.b64 %0, {%1, %2};" : "=l"(d) : "f"(lo), "f"(hi))
#define UNPACK2(lo,hi,v) asm("mov.b64 {%0, %1}, %2;" : "=f"(lo), "=f"(hi) : "l"(v))

#define DOT8(res, X, Y) do { \
    u64 _p; MUL2(_p, X[0], Y[0]); FMA2(_p, X[1], Y[1], _p); \
    FMA2(_p, X[2], Y[2], _p);     FMA2(_p, X[3], Y[3], _p); \
    float _lo, _hi; UNPACK2(_lo, _hi, _p); res = _lo + _hi; } while(0)

#define RED8(x) do { \
    x += __shfl_xor_sync(0xffffffffu, x, 1); \
    x += __shfl_xor_sync(0xffffffffu, x, 2); \
    x += __shfl_xor_sync(0xffffffffu, x, 4); } while(0)

#define LD4x2(dst, ptr) do { \
    const ulonglong2* _p = (const ulonglong2*)(ptr); \
    ulonglong2 _x0 = _p[0], _x1 = _p[1]; \
    dst[0]=_x0.x; dst[1]=_x0.y; dst[2]=_x1.x; dst[3]=_x1.y; } while(0)

__global__ void __launch_bounds__(64, 1) wkv7_kernel(
    const float* __restrict__ rr, const float* __restrict__ ww,
    const float* __restrict__ kk, const float* __restrict__ vv_,
    const float* __restrict__ aa, const float* __restrict__ bb,
    const float* __restrict__ s0, float* __restrict__ y, float* __restrict__ sout)
{
    const int blk   = blockIdx.x;
    const int h     = blk >> 2;
    const int q     = blk & 3;
    const int tid   = threadIdx.x;
    const int warp  = tid >> 5;          // 0..1
    const int lane  = tid & 31;
    const int lane8 = lane & 7;
    const int g     = lane >> 3;         // 0..3 group
    const int j0    = lane8 * 8;
    const int hbase = h * HS;
    const int r0    = q * 16 + warp * 8 + g * 2;  // rows r0, r0+1

    __shared__ __align__(16) float ring[2][DEPTH][STRIDE];

    // State: two rows, each 4 u64 (8 floats)
    u64 sA[4], sB[4];
    {
        const float* sp = s0 + ((size_t)h * HS + r0) * HS + j0;
        LD4x2(sA, sp);
        LD4x2(sB, sp + HS);
    }

    // cp.async lane routing: 3 rounds of 16B per lane
    const float *g1, *g2, *g3 = 0;
    uint32_t o1, o2, o3 = 0;
    if (lane < 16) { g1 = ww + hbase + lane * 4;        o1 = 0   + lane * 4; }
    else           { g1 = kk + hbase + (lane - 16) * 4; o1 = 64  + (lane - 16) * 4; }
    if (lane < 16) { g2 = aa + hbase + lane * 4;        o2 = 128 + lane * 4; }
    else           { g2 = bb + hbase + (lane - 16) * 4; o2 = 192 + (lane - 16) * 4; }
    if (lane < 16)      { g3 = rr + hbase + lane * 4;                      o3 = 256 + lane * 4; }
    else if (lane < 18) { g3 = vv_ + hbase + q * 16 + warp * 8 + (lane - 16) * 4; o3 = 320 + (lane - 16) * 4; }

#define ISSUE(tt, ss) do { \
    size_t _off = (size_t)(tt) * DIM; \
    uint32_t _sb = smem_u32(&ring[warp][ss][0]); \
    asm volatile("cp.async.cg.shared.global [%0], [%1], 16;" :: "r"(_sb + o1*4u), "l"(g1 + _off)); \
    asm volatile("cp.async.cg.shared.global [%0], [%1], 16;" :: "r"(_sb + o2*4u), "l"(g2 + _off)); \
    if (g3) asm volatile("cp.async.cg.shared.global [%0], [%1], 16;" :: "r"(_sb + o3*4u), "l"(g3 + _off)); \
    asm volatile("cp.async.commit_group;"); \
} while(0)

    // Prologue: fill ring
    #pragma unroll
    for (int i = 0; i < DEPTH; i++) ISSUE(i, i);

    // a_0 into registers via direct LDG (chain-critical operand, prefetched)
    u64 a2[4];
    LD4x2(a2, aa + hbase + j0);

    float yv0 = 0.f, yv1 = 0.f;   // deferred y partials (t-1)

    for (int t = 0; t < TLEN; t++) {
        asm volatile("cp.async.wait_group 6;");
        __syncwarp();

        const float* sl  = &ring[warp][t & (DEPTH-1)][0];
        const float* sln = &ring[warp][(t+1) & (DEPTH-1)][0];

        // sa dots for both rows (a_t already in regs) — start chain immediately
        float sa0, sa1;
        DOT8(sa0, sA, a2);
        DOT8(sa1, sB, a2);
        RED8(sa0);
        RED8(sa1);

        // meanwhile: finalize deferred y_{t-1}
        {
            float u0 = yv0, u1 = yv1;
            RED8(u0);
            RED8(u1);
            int tprev = (t > 0) ? (t - 1) : 0;
            if (lane8 == 0) *(float2*)&y[(size_t)tprev * DIM + hbase + r0] = make_float2(u0, u1);
        }

        // load this step's elementwise operands (slack: RED takes ~84 cyc)
        u64 w2[4], k2[4], b2[4], r2[4];
        LD4x2(w2, sl + j0);
        LD4x2(k2, sl + 64 + j0);
        LD4x2(b2, sl + 192 + j0);
        LD4x2(r2, sl + 256 + j0);
        const float2 vpair = *(const float2*)(sl + 320 + g * 2);

        // prefetch a_{t+1} (slot t+1 is forced-complete by wait_group 6)
        LD4x2(a2, sln + 128 + j0);

        // state update + y partial, both rows
        u64 v0b, v1b, sa0b, sa1b;
        PACK2(v0b, vpair.x, vpair.x); PACK2(v1b, vpair.y, vpair.y);
        PACK2(sa0b, sa0, sa0);        PACK2(sa1b, sa1, sa1);

        u64 yp0, yp1;
        #pragma unroll
        for (int i = 0; i < 4; i++) {
            u64 t0; MUL2(t0, sA[i], w2[i]);
            FMA2(t0, v0b, k2[i], t0);
            FMA2(sA[i], sa0b, b2[i], t0);
            u64 t1; MUL2(t1, sB[i], w2[i]);
            FMA2(t1, v1b, k2[i], t1);
            FMA2(sB[i], sa1b, b2[i], t1);
        }
        MUL2(yp0, sA[0], r2[0]); FMA2(yp0, sA[1], r2[1], yp0);
        FMA2(yp0, sA[2], r2[2], yp0); FMA2(yp0, sA[3], r2[3], yp0);
        MUL2(yp1, sB[0], r2[0]); FMA2(yp1, sB[1], r2[1], yp1);
        FMA2(yp1, sB[2], r2[2], yp1); FMA2(yp1, sB[3], r2[3], yp1);
        {
            float l0, h0, l1, h1;
            UNPACK2(l0, h0, yp0); UNPACK2(l1, h1, yp1);
            yv0 = l0 + h0; yv1 = l1 + h1;
        }

        // refill ring
        int tn = t + DEPTH; if (tn > TLEN - 1) tn = TLEN - 1;
        ISSUE(tn, t & (DEPTH-1));
    }

    // Epilogue: y_{TLEN-1}
    {
        RED8(yv0);
        RED8(yv1);
        if (lane8 == 0) *(float2*)&y[(size_t)(TLEN-1) * DIM + hbase + r0] = make_float2(yv0, yv1);
    }

    // Final state
    {
        float* sp = sout + ((size_t)h * HS + r0) * HS + j0;
        ulonglong2* p0 = (ulonglong2*)sp;
        ulonglong2* p1 = (ulonglong2*)(sp + HS);
        ulonglong2 x;
        x.x = sA[0]; x.y = sA[1]; p0[0] = x;
        x.x = sA[2]; x.y = sA[3]; p0[1] = x;
        x.x = sB[0]; x.y = sB[1]; p1[0] = x;
        x.x = sB[2]; x.y = sB[3]; p1[1] = x;
    }
}

extern "C" void kernel_launch(void* const* d_in, const int* in_sizes, int n_in,
                              void* d_out, int out_size) {
    int o = (n_in >= 8) ? 1 : 0;
    const float* r  = (const float*)d_in[o + 0];
    const float* w  = (const float*)d_in[o + 1];
    const float* k  = (const float*)d_in[o + 2];
    const float* v  = (const float*)d_in[o + 3];
    const float* a  = (const float*)d_in[o + 4];
    const float* b  = (const float*)d_in[o + 5];
    const float* s0 = (const float*)d_in[o + 6];

    float* y    = (float*)d_out;                  // x: [T, H, 1, N]
    float* sout = y + (size_t)TLEN * DIM;         // state2_out: [H, N, N]

    wkv7_kernel<<<128, 64>>>(r, w, k, v, a, b, s0, y, sout);
}

// round 6
// speedup vs baseline: 3.7706x; 1.1389x over previous
#include <cuda_runtime.h>
#include <cstdint>

#define TLEN 4096
#define NH 32
#define HS 64
#define DIM (NH*HS)
#define DEPTH 8
#define STRIDE 336   // floats/slot: w64|k64|a64|b64|r64|v8|pad

// grid=128 (32 heads x 4 quarters), block=64 = 2 warps. Warp = 4 groups x 8
// lanes; lane owns TWO rows' j-slices (16 state floats as f32x2).
// cp.async ring DEPTH=8/warp. Outer loop unrolled 8x so ring slots are
// compile-time constants (no per-step address math), tail peeled.

__device__ __forceinline__ uint32_t smem_u32(const void* p) {
    return (uint32_t)__cvta_generic_to_shared(p);
}

typedef unsigned long long u64;

#define MUL2(d,a,b)   asm("mul.rn.f32x2 %0, %1, %2;"     : "=l"(d) : "l"(a), "l"(b))
#define FMA2(d,a,b,c) asm("fma.rn.f32x2 %0, %1, %2, %3;" : "=l"(d) : "l"(a), "l"(b), "l"(c))
#define PACK2(d,lo,hi)   asm("mov.b64 %0, {%1, %2};" : "=l"(d) : "f"(lo), "f"(hi))
#define UNPACK2(lo,hi,v) asm("mov.b64 {%0, %1}, %2;" : "=f"(lo), "=f"(hi) : "l"(v))

#define DOT8(res, X, Y) do { \
    u64 _p; MUL2(_p, X[0], Y[0]); FMA2(_p, X[1], Y[1], _p); \
    FMA2(_p, X[2], Y[2], _p);     FMA2(_p, X[3], Y[3], _p); \
    float _lo, _hi; UNPACK2(_lo, _hi, _p); res = _lo + _hi; } while(0)

#define RED8(x) do { \
    x += __shfl_xor_sync(0xffffffffu, x, 1); \
    x += __shfl_xor_sync(0xffffffffu, x, 2); \
    x += __shfl_xor_sync(0xffffffffu, x, 4); } while(0)

#define LD4x2(dst, ptr) do { \
    const ulonglong2* _p = (const ulonglong2*)(ptr); \
    ulonglong2 _x0 = _p[0], _x1 = _p[1]; \
    dst[0]=_x0.x; dst[1]=_x0.y; dst[2]=_x1.x; dst[3]=_x1.y; } while(0)

__global__ void __launch_bounds__(64, 1) wkv7_kernel(
    const float* __restrict__ rr, const float* __restrict__ ww,
    const float* __restrict__ kk, const float* __restrict__ vv_,
    const float* __restrict__ aa, const float* __restrict__ bb,
    const float* __restrict__ s0, float* __restrict__ y, float* __restrict__ sout)
{
    const int blk   = blockIdx.x;
    const int h     = blk >> 2;
    const int q     = blk & 3;
    const int tid   = threadIdx.x;
    const int warp  = tid >> 5;
    const int lane  = tid & 31;
    const int lane8 = lane & 7;
    const int g     = lane >> 3;
    const int j0    = lane8 * 8;
    const int hbase = h * HS;
    const int r0    = q * 16 + warp * 8 + g * 2;

    __shared__ __align__(16) float ring[2][DEPTH][STRIDE];

    u64 sA[4], sB[4];
    {
        const float* sp = s0 + ((size_t)h * HS + r0) * HS + j0;
        LD4x2(sA, sp);
        LD4x2(sB, sp + HS);
    }

    // cp.async lane routing
    const float *g1, *g2, *g3 = 0;
    uint32_t o1, o2, o3 = 0;
    if (lane < 16) { g1 = ww + hbase + lane * 4;        o1 = 0   + lane * 4; }
    else           { g1 = kk + hbase + (lane - 16) * 4; o1 = 64  + (lane - 16) * 4; }
    if (lane < 16) { g2 = aa + hbase + lane * 4;        o2 = 128 + lane * 4; }
    else           { g2 = bb + hbase + (lane - 16) * 4; o2 = 192 + (lane - 16) * 4; }
    if (lane < 16)      { g3 = rr + hbase + lane * 4;                      o3 = 256 + lane * 4; }
    else if (lane < 18) { g3 = vv_ + hbase + q * 16 + warp * 8 + (lane - 16) * 4; o3 = 320 + (lane - 16) * 4; }

#define ISSUE(tt, ss) do { \
    size_t _off = (size_t)(tt) * DIM; \
    uint32_t _sb = smem_u32(&ring[warp][ss][0]); \
    asm volatile("cp.async.cg.shared.global [%0], [%1], 16;" :: "r"(_sb + o1*4u), "l"(g1 + _off)); \
    asm volatile("cp.async.cg.shared.global [%0], [%1], 16;" :: "r"(_sb + o2*4u), "l"(g2 + _off)); \
    if (g3) asm volatile("cp.async.cg.shared.global [%0], [%1], 16;" :: "r"(_sb + o3*4u), "l"(g3 + _off)); \
    asm volatile("cp.async.commit_group;"); \
} while(0)

    #pragma unroll
    for (int i = 0; i < DEPTH; i++) ISSUE(i, i);

    u64 a2[4];
    LD4x2(a2, aa + hbase + j0);

    float yv0 = 0.f, yv1 = 0.f;
    float* const ybase = y + hbase + r0;

// Core step body. SLOT/SLOTN are compile-time ring slot indices.
#define STEPBODY(T, SLOT, SLOTN) do { \
    const float* sl  = &ring[warp][SLOT][0]; \
    const float* sln = &ring[warp][SLOTN][0]; \
    float sa0, sa1; \
    DOT8(sa0, sA, a2); \
    DOT8(sa1, sB, a2); \
    RED8(sa0); \
    RED8(sa1); \
    { \
        float u0 = yv0, u1 = yv1; \
        RED8(u0); \
        RED8(u1); \
        int tprev = (T) - ((T) != 0); \
        if (lane8 == 0) *(float2*)&ybase[(size_t)tprev * DIM] = make_float2(u0, u1); \
    } \
    u64 w2[4], k2[4], b2[4], r2[4]; \
    LD4x2(w2, sl + j0); \
    LD4x2(k2, sl + 64 + j0); \
    LD4x2(b2, sl + 192 + j0); \
    LD4x2(r2, sl + 256 + j0); \
    const float2 vpair = *(const float2*)(sl + 320 + g * 2); \
    LD4x2(a2, sln + 128 + j0); \
    u64 v0b, v1b, sa0b, sa1b; \
    PACK2(v0b, vpair.x, vpair.x); PACK2(v1b, vpair.y, vpair.y); \
    PACK2(sa0b, sa0, sa0);        PACK2(sa1b, sa1, sa1); \
    _Pragma("unroll") \
    for (int i = 0; i < 4; i++) { \
        u64 t0; MUL2(t0, sA[i], w2[i]); \
        FMA2(t0, v0b, k2[i], t0); \
        FMA2(sA[i], sa0b, b2[i], t0); \
        u64 t1; MUL2(t1, sB[i], w2[i]); \
        FMA2(t1, v1b, k2[i], t1); \
        FMA2(sB[i], sa1b, b2[i], t1); \
    } \
    u64 yp0, yp1; \
    MUL2(yp0, sA[0], r2[0]); FMA2(yp0, sA[1], r2[1], yp0); \
    FMA2(yp0, sA[2], r2[2], yp0); FMA2(yp0, sA[3], r2[3], yp0); \
    MUL2(yp1, sB[0], r2[0]); FMA2(yp1, sB[1], r2[1], yp1); \
    FMA2(yp1, sB[2], r2[2], yp1); FMA2(yp1, sB[3], r2[3], yp1); \
    { \
        float l0, h0, l1, h1; \
        UNPACK2(l0, h0, yp0); UNPACK2(l1, h1, yp1); \
        yv0 = l0 + h0; yv1 = l1 + h1; \
    } \
} while(0)

    // Main: t in [0, TLEN-8), 8x unrolled, constant slots, unclamped refill.
    for (int tb = 0; tb < TLEN - DEPTH; tb += DEPTH) {
        #pragma unroll
        for (int u = 0; u < DEPTH; u++) {
            const int t = tb + u;
            asm volatile("cp.async.wait_group 6;");
            __syncwarp();
            STEPBODY(t, u, (u + 1) & (DEPTH - 1));
            ISSUE(t + DEPTH, u);
        }
    }

    // Tail: last 8 steps, all data already staged.
    asm volatile("cp.async.wait_group 0;");
    __syncwarp();
    #pragma unroll
    for (int u = 0; u < DEPTH; u++) {
        const int t = TLEN - DEPTH + u;
        STEPBODY(t, u, (u + 1) & (DEPTH - 1));  // u=7 reads stale a2: unused
    }

    // Epilogue: y_{TLEN-1}
    {
        RED8(yv0);
        RED8(yv1);
        if (lane8 == 0) *(float2*)&ybase[(size_t)(TLEN-1) * DIM] = make_float2(yv0, yv1);
    }

    // Final state
    {
        float* sp = sout + ((size_t)h * HS + r0) * HS + j0;
        ulonglong2* p0 = (ulonglong2*)sp;
        ulonglong2* p1 = (ulonglong2*)(sp + HS);
        ulonglong2 x;
        x.x = sA[0]; x.y = sA[1]; p0[0] = x;
        x.x = sA[2]; x.y = sA[3]; p0[1] = x;
        x.x = sB[0]; x.y = sB[1]; p1[0] = x;
        x.x = sB[2]; x.y = sB[3]; p1[1] = x;
    }
}

extern "C" void kernel_launch(void* const* d_in, const int* in_sizes, int n_in,
                              void* d_out, int out_size) {
    int o = (n_in >= 8) ? 1 : 0;
    const float* r  = (const float*)d_in[o + 0];
    const float* w  = (const float*)d_in[o + 1];
    const float* k  = (const float*)d_in[o + 2];
    const float* v  = (const float*)d_in[o + 3];
    const float* a  = (const float*)d_in[o + 4];
    const float* b  = (const float*)d_in[o + 5];
    const float* s0 = (const float*)d_in[o + 6];

    float* y    = (float*)d_out;                  // x: [T, H, 1, N]
    float* sout = y + (size_t)TLEN * DIM;         // state2_out: [H, N, N]

    wkv7_kernel<<<128, 64>>>(r, w, k, v, a, b, s0, y, sout);
}